// round 1
// baseline (speedup 1.0000x reference)
#include <cuda_runtime.h>

#define B_   16
#define T_   512
#define C_   8
#define S_   64
#define KSZ_ 32
#define TOUT 481
#define EPSF 1e-8f

// Scratch (allocation-free rule: __device__ globals)
__device__ float g_xt[B_ * C_ * T_];     // x normalized, transposed: [b][ch][t]
__device__ float g_kn[S_ * KSZ_ * C_];   // normalized kernel [s][k][c]
__device__ float g_q2[S_ * KSZ_];        // sum_c kn^2 per (s,k)

// ---------------------------------------------------------------------------
// Prep: blocks [0,128) normalize x per (b,ch) over T and transpose;
//       blocks [128,192) normalize kernel per s over (KSZ*C) and compute q2.
// ---------------------------------------------------------------------------
__global__ __launch_bounds__(256) void lsd_prep(const float* __restrict__ x,
                                                const float* __restrict__ kern) {
    const int bid = blockIdx.x;
    const int tid = threadIdx.x;
    __shared__ float red0[256];
    __shared__ float red1[256];
    __shared__ float kns[256];

    if (bid < B_ * C_) {
        const int b = bid >> 3, ch = bid & 7;
        // 512 elements, 2 per thread
        const float v0 = x[(b * T_ + tid) * C_ + ch];
        const float v1 = x[(b * T_ + tid + 256) * C_ + ch];
        red0[tid] = v0 + v1;
        red1[tid] = v0 * v0 + v1 * v1;
        __syncthreads();
        #pragma unroll
        for (int off = 128; off > 0; off >>= 1) {
            if (tid < off) { red0[tid] += red0[tid + off]; red1[tid] += red1[tid + off]; }
            __syncthreads();
        }
        const float mean = red0[0] * (1.0f / T_);
        const float var  = red1[0] * (1.0f / T_) - mean * mean;
        const float inv  = 1.0f / (sqrtf(fmaxf(var, 0.0f)) + EPSF);
        float* xr = &g_xt[(b * C_ + ch) * T_];
        xr[tid]       = (v0 - mean) * inv;
        xr[tid + 256] = (v1 - mean) * inv;
    } else {
        const int s = bid - B_ * C_;
        const float v = kern[s * 256 + tid];
        red0[tid] = v;
        red1[tid] = v * v;
        __syncthreads();
        #pragma unroll
        for (int off = 128; off > 0; off >>= 1) {
            if (tid < off) { red0[tid] += red0[tid + off]; red1[tid] += red1[tid + off]; }
            __syncthreads();
        }
        const float mean = red0[0] * (1.0f / 256.0f);
        const float var  = red1[0] * (1.0f / 256.0f) - mean * mean;
        const float inv  = 1.0f / (sqrtf(fmaxf(var, 0.0f)) + EPSF);
        const float kn = (v - mean) * inv;
        g_kn[s * 256 + tid] = kn;
        kns[tid] = kn;
        __syncthreads();
        if (tid < KSZ_) {
            float q2 = 0.0f;
            #pragma unroll
            for (int c = 0; c < 8; c++) {
                const float t = kns[tid * 8 + c];
                q2 = fmaf(t, t, q2);
            }
            g_q2[s * KSZ_ + tid] = q2;
        }
    }
}

// ---------------------------------------------------------------------------
// Main: block = (b, 32-t tile). 128 threads: k = tid&31, t-group = tid>>5,
// each thread computes 8 consecutive t outputs for one k.
// dist = p2 - 2*dot + q2 ; min over s is p2 + min_s(q2 - 2*dot).
// ---------------------------------------------------------------------------
__global__ __launch_bounds__(128) void lsd_main(float* __restrict__ out) {
    const int tid = threadIdx.x;
    const int k  = tid & 31;
    const int tg = tid >> 5;                 // 0..3
    const int b  = blockIdx.y;
    const int t_base = blockIdx.x * 32 + tg * 8;
    const int ch = k >> 2;
    const int m  = k & 3;
    const int wstart = t_base + 8 * m;

    const float* __restrict__ xrow = &g_xt[(b * C_ + ch) * T_];
    float w[15];
    #pragma unroll
    for (int i = 0; i < 15; i++) {
        int idx = wstart + i;
        if (idx > T_ - 1) idx = T_ - 1;      // clamp (padding lanes only)
        w[i] = __ldg(&xrow[idx]);
    }

    float p2[8];
    #pragma unroll
    for (int j = 0; j < 8; j++) {
        float a = 0.0f;
        #pragma unroll
        for (int c = 0; c < 8; c++) a = fmaf(w[j + c], w[j + c], a);
        p2[j] = a;
    }

    float mn[8];
    #pragma unroll
    for (int j = 0; j < 8; j++) mn[j] = 3.4e38f;

    const float4* __restrict__ knp = (const float4*)g_kn;
    const float*  __restrict__ q2p = g_q2;

    #pragma unroll 4
    for (int s = 0; s < S_; s++) {
        const int sk = s * 32 + k;
        const float4 qa = __ldg(&knp[sk * 2]);
        const float4 qb = __ldg(&knp[sk * 2 + 1]);
        const float  q2 = __ldg(&q2p[sk]);
        #pragma unroll
        for (int j = 0; j < 8; j++) {
            float d;
            d = w[j]     * qa.x;
            d = fmaf(w[j + 1], qa.y, d);
            d = fmaf(w[j + 2], qa.z, d);
            d = fmaf(w[j + 3], qa.w, d);
            d = fmaf(w[j + 4], qb.x, d);
            d = fmaf(w[j + 5], qb.y, d);
            d = fmaf(w[j + 6], qb.z, d);
            d = fmaf(w[j + 7], qb.w, d);
            mn[j] = fminf(mn[j], fmaf(-2.0f, d, q2));
        }
    }

    #pragma unroll
    for (int j = 0; j < 8; j++) {
        const int t = t_base + j;
        if (t < TOUT) out[(b * TOUT + t) * KSZ_ + k] = p2[j] + mn[j];
    }
}

extern "C" void kernel_launch(void* const* d_in, const int* in_sizes, int n_in,
                              void* d_out, int out_size) {
    const float* x    = (const float*)d_in[0];   // (16, 512, 8) f32
    const float* kern = (const float*)d_in[1];   // (64, 32, 8) f32
    float* out = (float*)d_out;                  // (16, 481, 32) f32

    lsd_prep<<<B_ * C_ + S_, 256>>>(x, kern);
    dim3 grid(16, B_);                           // 16 t-tiles of 32, per batch
    lsd_main<<<grid, 128>>>(out);
}

// round 2
// speedup vs baseline: 1.2886x; 1.2886x over previous
#include <cuda_runtime.h>

#define B_   16
#define T_   512
#define C_   8
#define S_   64
#define KSZ_ 32
#define TOUT 481
#define EPSF 1e-8f

// Scratch (allocation-free rule: __device__ globals)
__device__ float g_xt[B_ * C_ * T_];     // x normalized, transposed: [b][ch][t]
__device__ float g_kn[S_ * KSZ_ * C_];   // normalized kernel [s][k][c]
__device__ float g_q2[S_ * KSZ_];        // sum_c kn^2 per (s,k)

// ---- packed f32x2 helpers (sm_100a) ---------------------------------------
__device__ __forceinline__ unsigned long long pk2(float lo, float hi) {
    unsigned long long r;
    asm("mov.b64 %0, {%1, %2};" : "=l"(r) : "f"(lo), "f"(hi));
    return r;
}
__device__ __forceinline__ unsigned long long fma2(unsigned long long a,
                                                   unsigned long long b,
                                                   unsigned long long c) {
    unsigned long long d;
    asm("fma.rn.f32x2 %0, %1, %2, %3;" : "=l"(d) : "l"(a), "l"(b), "l"(c));
    return d;
}
__device__ __forceinline__ unsigned long long mul2(unsigned long long a,
                                                   unsigned long long b) {
    unsigned long long d;
    asm("mul.rn.f32x2 %0, %1, %2;" : "=l"(d) : "l"(a), "l"(b));
    return d;
}
__device__ __forceinline__ float hsum2(unsigned long long v) {
    float lo, hi;
    asm("mov.b64 {%0, %1}, %2;" : "=f"(lo), "=f"(hi) : "l"(v));
    return lo + hi;
}

// ---------------------------------------------------------------------------
// Prep: blocks [0,128) normalize x per (b,ch) over T and transpose;
//       blocks [128,192) normalize kernel per s over (KSZ*C) and compute q2.
// ---------------------------------------------------------------------------
__global__ __launch_bounds__(256) void lsd_prep(const float* __restrict__ x,
                                                const float* __restrict__ kern) {
    const int bid = blockIdx.x;
    const int tid = threadIdx.x;
    __shared__ float red0[256];
    __shared__ float red1[256];
    __shared__ float kns[256];

    if (bid < B_ * C_) {
        const int b = bid >> 3, ch = bid & 7;
        const float v0 = x[(b * T_ + tid) * C_ + ch];
        const float v1 = x[(b * T_ + tid + 256) * C_ + ch];
        red0[tid] = v0 + v1;
        red1[tid] = v0 * v0 + v1 * v1;
        __syncthreads();
        #pragma unroll
        for (int off = 128; off > 0; off >>= 1) {
            if (tid < off) { red0[tid] += red0[tid + off]; red1[tid] += red1[tid + off]; }
            __syncthreads();
        }
        const float mean = red0[0] * (1.0f / T_);
        const float var  = red1[0] * (1.0f / T_) - mean * mean;
        const float inv  = 1.0f / (sqrtf(fmaxf(var, 0.0f)) + EPSF);
        float* xr = &g_xt[(b * C_ + ch) * T_];
        xr[tid]       = (v0 - mean) * inv;
        xr[tid + 256] = (v1 - mean) * inv;
    } else {
        const int s = bid - B_ * C_;
        const float v = kern[s * 256 + tid];
        red0[tid] = v;
        red1[tid] = v * v;
        __syncthreads();
        #pragma unroll
        for (int off = 128; off > 0; off >>= 1) {
            if (tid < off) { red0[tid] += red0[tid + off]; red1[tid] += red1[tid + off]; }
            __syncthreads();
        }
        const float mean = red0[0] * (1.0f / 256.0f);
        const float var  = red1[0] * (1.0f / 256.0f) - mean * mean;
        const float inv  = 1.0f / (sqrtf(fmaxf(var, 0.0f)) + EPSF);
        const float kn = (v - mean) * inv;
        g_kn[s * 256 + tid] = kn;
        kns[tid] = kn;
        __syncthreads();
        if (tid < KSZ_) {
            float q2 = 0.0f;
            #pragma unroll
            for (int c = 0; c < 8; c++) {
                const float t = kns[tid * 8 + c];
                q2 = fmaf(t, t, q2);
            }
            g_q2[s * KSZ_ + tid] = q2;
        }
    }
}

// ---------------------------------------------------------------------------
// Main: block = (b, 16-t tile). 256 threads:
//   k  = tid & 31          (output channel-window index)
//   tg = (tid >> 5) & 3    (t-subgroup, 4 consecutive t each)
//   sg = tid >> 7          (S-half: s in [32*sg, 32*sg+32))
// Each thread: 4 t-outputs over 32 prototypes; halves merged via smem min.
// dist = p2 - 2*dot + q2 ; min over s is p2 + min_s(q2 - 2*dot).
// Dot products use packed f32x2 FMAs; q-pairs (q_c,q_{c+1}) are the natural
// memory layout of g_kn so no packing is needed on the q side.
// ---------------------------------------------------------------------------
__global__ __launch_bounds__(256) void lsd_main(float* __restrict__ out) {
    const int tid = threadIdx.x;
    const int k   = tid & 31;
    const int tg  = (tid >> 5) & 3;
    const int sg  = tid >> 7;
    const int b   = blockIdx.y;
    const int t_base = blockIdx.x * 16 + tg * 4;
    const int ch = k >> 2;
    const int m  = k & 3;
    const int wstart = t_base + 8 * m;

    __shared__ float s_mn[128 * 4];

    // window: j in [0,4), c in [0,8) -> w[0..10]
    const float* __restrict__ xrow = &g_xt[(b * C_ + ch) * T_];
    float w[11];
    #pragma unroll
    for (int i = 0; i < 11; i++) {
        int idx = wstart + i;
        if (idx > T_ - 1) idx = T_ - 1;      // clamp (padding lanes only)
        w[i] = __ldg(&xrow[idx]);
    }

    // packed sliding pairs a[i] = (w[i], w[i+1]); dot uses a[j+2e], e=0..3
    unsigned long long a[10];
    #pragma unroll
    for (int i = 0; i < 10; i++) a[i] = pk2(w[i], w[i + 1]);

    // p2[j] = sum_c w[j+c]^2 via packed squares + horizontal sum
    float p2[4];
    #pragma unroll
    for (int j = 0; j < 4; j++) {
        unsigned long long acc = mul2(a[j], a[j]);
        acc = fma2(a[j + 2], a[j + 2], acc);
        acc = fma2(a[j + 4], a[j + 4], acc);
        acc = fma2(a[j + 6], a[j + 6], acc);
        p2[j] = hsum2(acc);
    }

    float mn[4];
    #pragma unroll
    for (int j = 0; j < 4; j++) mn[j] = 3.4e38f;

    const ulonglong2* __restrict__ knq = (const ulonglong2*)g_kn;
    const float* __restrict__ q2p = g_q2;

    const int s0 = sg * 32;
    #pragma unroll 4
    for (int s = s0; s < s0 + 32; s++) {
        const int sk = s * 32 + k;
        const ulonglong2 QA = knq[sk * 2];       // (q0,q1),(q2,q3)
        const ulonglong2 QB = knq[sk * 2 + 1];   // (q4,q5),(q6,q7)
        const float q2 = __ldg(&q2p[sk]);
        #pragma unroll
        for (int j = 0; j < 4; j++) {
            unsigned long long dp = mul2(a[j], QA.x);
            dp = fma2(a[j + 2], QA.y, dp);
            dp = fma2(a[j + 4], QB.x, dp);
            dp = fma2(a[j + 6], QB.y, dp);
            const float d = hsum2(dp);
            mn[j] = fminf(mn[j], fmaf(-2.0f, d, q2));
        }
    }

    // merge the two S-halves
    if (sg == 1) {
        #pragma unroll
        for (int j = 0; j < 4; j++) s_mn[(tid - 128) * 4 + j] = mn[j];
    }
    __syncthreads();
    if (sg == 0) {
        #pragma unroll
        for (int j = 0; j < 4; j++) {
            const int t = t_base + j;
            if (t < TOUT) {
                const float v = fminf(mn[j], s_mn[tid * 4 + j]);
                out[(b * TOUT + t) * KSZ_ + k] = p2[j] + v;
            }
        }
    }
}

extern "C" void kernel_launch(void* const* d_in, const int* in_sizes, int n_in,
                              void* d_out, int out_size) {
    const float* x    = (const float*)d_in[0];   // (16, 512, 8) f32
    const float* kern = (const float*)d_in[1];   // (64, 32, 8) f32
    float* out = (float*)d_out;                  // (16, 481, 32) f32

    lsd_prep<<<B_ * C_ + S_, 256>>>(x, kern);
    dim3 grid(31, B_);                           // 31 t-tiles of 16, per batch
    lsd_main<<<grid, 256>>>(out);
}